// round 16
// baseline (speedup 1.0000x reference)
#include <cuda_runtime.h>
#include <math.h>
#include <stdint.h>

#define NN_MAX 100000
#define ADIM   1000

// ------------------------- scratch (no runtime alloc) -----------------------
__device__ float g_h   [(size_t)NN_MAX*128];
__device__ float g_agg [(size_t)NN_MAX*128];
__device__ float g_h1  [(size_t)NN_MAX*256];
__device__ float g_h2  [(size_t)NN_MAX*256];
__device__ float g_deg [NN_MAX];
__device__ float g_dinv[NN_MAX];
__device__ float g_conc[NN_MAX];
__device__ float g_lg  [NN_MAX];

// ------------------------- threefry2x32 (JAX-exact) -------------------------
struct K2 { unsigned a, b; };

__device__ __forceinline__ void tf_round(unsigned &x0, unsigned &x1, int r) {
    x0 += x1;
    x1 = (x1 << r) | (x1 >> (32 - r));
    x1 ^= x0;
}
__device__ __forceinline__ K2 tf_block(unsigned k0, unsigned k1, unsigned x0, unsigned x1) {
    unsigned k2 = k0 ^ k1 ^ 0x1BD11BDAu;
    x0 += k0; x1 += k1;
    tf_round(x0,x1,13); tf_round(x0,x1,15); tf_round(x0,x1,26); tf_round(x0,x1,6);
    x0 += k1; x1 += k2 + 1u;
    tf_round(x0,x1,17); tf_round(x0,x1,29); tf_round(x0,x1,16); tf_round(x0,x1,24);
    x0 += k2; x1 += k0 + 2u;
    tf_round(x0,x1,13); tf_round(x0,x1,15); tf_round(x0,x1,26); tf_round(x0,x1,6);
    x0 += k0; x1 += k1 + 3u;
    tf_round(x0,x1,17); tf_round(x0,x1,29); tf_round(x0,x1,16); tf_round(x0,x1,24);
    x0 += k1; x1 += k2 + 4u;
    tf_round(x0,x1,13); tf_round(x0,x1,15); tf_round(x0,x1,26); tf_round(x0,x1,6);
    x0 += k2; x1 += k0 + 5u;
    K2 r; r.a = x0; r.b = x1; return r;
}
__device__ __forceinline__ unsigned rbits(K2 k) {
    K2 r = tf_block(k.a, k.b, 0u, 0u);
    return r.a ^ r.b;
}
__device__ __forceinline__ void split2(K2 k, K2 &o0, K2 &o1) {
    o0 = tf_block(k.a, k.b, 0u, 0u);
    o1 = tf_block(k.a, k.b, 0u, 1u);
}
__device__ __forceinline__ void split3(K2 k, K2 &o0, K2 &o1, K2 &o2) {
    o0 = tf_block(k.a, k.b, 0u, 0u);
    o1 = tf_block(k.a, k.b, 0u, 1u);
    o2 = tf_block(k.a, k.b, 0u, 2u);
}
__device__ __forceinline__ K2 split_big(K2 k, unsigned i) {
    return tf_block(k.a, k.b, 0u, i);
}
__device__ __forceinline__ float u01(K2 k) {
    unsigned bits = rbits(k);
    return __uint_as_float((bits >> 9) | 0x3f800000u) - 1.0f;
}
__device__ __forceinline__ float erfinv_xla(float x) {
    float xx = __fmul_rn(x, x);
    float w = (float)(-log1p(-(double)xx));
    float p;
    if (w < 5.0f) {
        w = __fsub_rn(w, 2.5f);
        p = 2.81022636e-08f;
        p = fmaf(p, w, 3.43273939e-07f);
        p = fmaf(p, w, -3.5233877e-06f);
        p = fmaf(p, w, -4.39150654e-06f);
        p = fmaf(p, w, 0.00021858087f);
        p = fmaf(p, w, -0.00125372503f);
        p = fmaf(p, w, -0.00417768164f);
        p = fmaf(p, w, 0.246640727f);
        p = fmaf(p, w, 1.50140941f);
    } else {
        w = __fsub_rn(__fsqrt_rn(w), 3.0f);
        p = -0.000200214257f;
        p = fmaf(p, w, 0.000100950558f);
        p = fmaf(p, w, 0.00134934322f);
        p = fmaf(p, w, -0.00367342844f);
        p = fmaf(p, w, 0.00573950773f);
        p = fmaf(p, w, -0.0076224613f);
        p = fmaf(p, w, 0.00943887047f);
        p = fmaf(p, w, 1.00167406f);
        p = fmaf(p, w, 2.83297682f);
    }
    return __fmul_rn(p, x);
}
__device__ __forceinline__ float nrm(K2 k) {
    float f = u01(k);
    const float lo = __uint_as_float(0xBF7FFFFFu);
    float v = __fadd_rn(__fmul_rn(f, 2.0f), lo);
    v = fmaxf(lo, v);
    return __fmul_rn(__uint_as_float(0x3FB504F3u), erfinv_xla(v));
}

// ------------------------- degree / norm ------------------------------------
__global__ void k_deg_init(int n) {
    int i = blockIdx.x * blockDim.x + threadIdx.x;
    if (i < n) g_deg[i] = 1.0f;
}
__global__ void k_deg_count(const int* __restrict__ dst, int E) {
    int e = blockIdx.x * blockDim.x + threadIdx.x;
    if (e < E) atomicAdd(&g_deg[dst[e]], 1.0f);
}
__global__ void k_dinv(int n) {
    int i = blockIdx.x * blockDim.x + threadIdx.x;
    if (i < n) g_dinv[i] = (float)(1.0 / sqrt((double)g_deg[i]));
}
__global__ void k_self(int n4) {
    int idx = blockIdx.x * blockDim.x + threadIdx.x;
    if (idx >= n4) return;
    int node = idx >> 5;
    float di = g_dinv[node];
    float n2 = __fmul_rn(di, di);
    float4 v = ((const float4*)g_h)[idx];
    float4 o;
    o.x = __fmul_rn(v.x, n2); o.y = __fmul_rn(v.y, n2);
    o.z = __fmul_rn(v.z, n2); o.w = __fmul_rn(v.w, n2);
    ((float4*)g_agg)[idx] = o;
}
__global__ void k_scatter(const int* __restrict__ src, const int* __restrict__ dst, int E) {
    int e = blockIdx.x * 8 + (threadIdx.x >> 5);
    if (e >= E) return;
    int lane = threadIdx.x & 31;
    int s = __ldg(&src[e]);
    int d = __ldg(&dst[e]);
    float norm = __fmul_rn(g_dinv[s], g_dinv[d]);
    float4 v = *(const float4*)(g_h + (size_t)s * 128 + lane * 4);
    float* out = g_agg + (size_t)d * 128 + lane * 4;
    float m0 = __fmul_rn(v.x, norm);
    float m1 = __fmul_rn(v.y, norm);
    float m2 = __fmul_rn(v.z, norm);
    float m3 = __fmul_rn(v.w, norm);
    asm volatile("red.global.add.v4.f32 [%0], {%1,%2,%3,%4};"
                 :: "l"(out), "f"(m0), "f"(m1), "f"(m2), "f"(m3) : "memory");
}
__global__ void k_prep(const float* __restrict__ x, const float* __restrict__ bc, int n4) {
    int idx = blockIdx.x * blockDim.x + threadIdx.x;
    if (idx >= n4) return;
    int c4 = (idx & 31);
    float4 g = ((const float4*)g_agg)[idx];
    float4 xv = ((const float4*)x)[idx];
    float4 b = ((const float4*)bc)[c4];
    float4 o;
    o.x = __fadd_rn(fmaxf(__fadd_rn(g.x, b.x), 0.f), xv.x);
    o.y = __fadd_rn(fmaxf(__fadd_rn(g.y, b.y), 0.f), xv.y);
    o.z = __fadd_rn(fmaxf(__fadd_rn(g.z, b.z), 0.f), xv.z);
    o.w = __fadd_rn(fmaxf(__fadd_rn(g.w, b.w), 0.f), xv.w);
    ((float4*)g_h)[idx] = o;
}

// ------------------------- 3xTF32 mma.sync GEMM -----------------------------
// R14 core with hi/lo interleaved as uint2 in smem: one LDS.64 fetches both
// halves of a fragment element (halves LDS instruction count).
// CTA 128x128, warp 32x64, 2 CTA/SM, K-slice 8, 2-buf smem.
// A: [row][k] uint2 pitch 12;  W: [k][col] uint2 pitch 132 (both conflict-free).
// EPI=0: C = A@W.  EPI=1: C = leaky(A@W + bout).
#define PSA2 12
#define PSW2 132

__device__ __forceinline__ uint32_t f2tf(float x) {
    uint32_t r;
    asm("cvt.rna.tf32.f32 %0, %1;" : "=r"(r) : "f"(x));
    return r;
}

#define MMA_TF32(c, a, b0, b1) \
    asm volatile("mma.sync.aligned.m16n8k8.row.col.f32.tf32.tf32.f32 " \
                 "{%0,%1,%2,%3}, {%4,%5,%6,%7}, {%8,%9}, {%0,%1,%2,%3};" \
                 : "+f"((c)[0]), "+f"((c)[1]), "+f"((c)[2]), "+f"((c)[3]) \
                 : "r"((a)[0]), "r"((a)[1]), "r"((a)[2]), "r"((a)[3]), \
                   "r"(b0), "r"(b1))

template<int K, int LDW, int LDA, int LDC, int EPI>
__global__ void __launch_bounds__(256, 2) k_gemm(const float* __restrict__ A,
                                                 const float* __restrict__ W,
                                                 const float* __restrict__ bout,
                                                 float* __restrict__ Cout, int N) {
    __shared__ uint2 sA2[2][128 * PSA2];
    __shared__ uint2 sW2[2][8 * PSW2];

    const int t    = threadIdx.x;
    const int row0 = blockIdx.x * 128;
    const int c0   = blockIdx.y * 128;
    const int S    = K / 8;

    // loader indices
    const int lr   = t >> 1;               // A row 0..127
    const int lk4  = (t & 1) * 4;          // A k-offset 0/4
    const int wk   = t >> 5;               // W k-row 0..7
    const int wc4  = (t & 31) * 4;         // W col
    const bool aok = (row0 + lr) < N;
    const float* Ap = A + (size_t)(row0 + lr) * LDA + lk4;
    const float* Wp = W + (size_t)wk * LDW + c0 + wc4;

    // compute indices
    const int lane = t & 31;
    const int g    = lane >> 2;
    const int tig  = lane & 3;
    const int wid  = t >> 5;
    const int wm   = wid & 3;              // 4 warps along M
    const int wn   = wid >> 2;             // 2 warps along N
    const int rowb = wm * 32;
    const int colb = wn * 64;

    float acc[2][8][4];
#pragma unroll
    for (int m = 0; m < 2; m++)
#pragma unroll
        for (int n = 0; n < 8; n++)
#pragma unroll
            for (int q = 0; q < 4; q++) acc[m][n][q] = 0.f;

    float4 va = make_float4(0.f, 0.f, 0.f, 0.f), vw;
    if (aok) va = *(const float4*)(Ap);
    vw = *(const float4*)(Wp);

    // split+store registers -> smem buffer b: interleaved (hi,lo) uint2 pairs
    auto sstore = [&](int b) {
        const float* vaf = (const float*)&va;
        const float* vwf = (const float*)&vw;
        uint32_t ha[4], la[4], hw[4], lw[4];
#pragma unroll
        for (int j = 0; j < 4; j++) {
            float x = vaf[j];
            ha[j] = f2tf(x);
            la[j] = f2tf(__fsub_rn(x, __uint_as_float(ha[j])));
            float y = vwf[j];
            hw[j] = f2tf(y);
            lw[j] = f2tf(__fsub_rn(y, __uint_as_float(hw[j])));
        }
        *(uint4*)&sA2[b][lr * PSA2 + lk4]     = make_uint4(ha[0], la[0], ha[1], la[1]);
        *(uint4*)&sA2[b][lr * PSA2 + lk4 + 2] = make_uint4(ha[2], la[2], ha[3], la[3]);
        *(uint4*)&sW2[b][wk * PSW2 + wc4]     = make_uint4(hw[0], lw[0], hw[1], lw[1]);
        *(uint4*)&sW2[b][wk * PSW2 + wc4 + 2] = make_uint4(hw[2], lw[2], hw[3], lw[3]);
    };

    sstore(0);
    __syncthreads();

    for (int s = 0; s < S; s++) {
        const int buf = s & 1;
        if (s + 1 < S) {
            int kc = (s + 1) * 8;
            va = make_float4(0.f, 0.f, 0.f, 0.f);
            if (aok) va = *(const float4*)(Ap + kc);
            vw = *(const float4*)(Wp + (size_t)kc * LDW);
        }

        // A fragments: one LDS.64 per (hi,lo) element pair
        uint32_t ah[2][4], al[2][4];
#pragma unroll
        for (int m = 0; m < 2; m++) {
            int rb = rowb + m * 16 + g;
            uint2 p0 = sA2[buf][rb * PSA2 + tig];
            uint2 p1 = sA2[buf][(rb + 8) * PSA2 + tig];
            uint2 p2 = sA2[buf][rb * PSA2 + tig + 4];
            uint2 p3 = sA2[buf][(rb + 8) * PSA2 + tig + 4];
            ah[m][0] = p0.x; al[m][0] = p0.y;
            ah[m][1] = p1.x; al[m][1] = p1.y;
            ah[m][2] = p2.x; al[m][2] = p2.y;
            ah[m][3] = p3.x; al[m][3] = p3.y;
        }
#pragma unroll
        for (int n = 0; n < 8; n++) {
            int col = colb + n * 8 + g;
            uint2 w0 = sW2[buf][tig * PSW2 + col];
            uint2 w1 = sW2[buf][(tig + 4) * PSW2 + col];
            uint32_t bh0 = w0.x, bl0 = w0.y;
            uint32_t bh1 = w1.x, bl1 = w1.y;
#pragma unroll
            for (int m = 0; m < 2; m++) {
                MMA_TF32(acc[m][n], ah[m], bh0, bh1);
                MMA_TF32(acc[m][n], ah[m], bl0, bl1);
                MMA_TF32(acc[m][n], al[m], bh0, bh1);
            }
        }

        if (s + 1 < S) sstore(buf ^ 1);
        __syncthreads();
    }

    // epilogue
#pragma unroll
    for (int m = 0; m < 2; m++) {
#pragma unroll
        for (int n = 0; n < 8; n++) {
            int rl  = row0 + rowb + m * 16 + g;
            int rh  = rl + 8;
            int col = c0 + colb + n * 8 + 2 * tig;
            float2 bv = make_float2(0.f, 0.f);
            if (EPI) bv = *(const float2*)(bout + col);
            float v0 = acc[m][n][0], v1 = acc[m][n][1];
            float v2 = acc[m][n][2], v3 = acc[m][n][3];
            if (EPI) {
                v0 = __fadd_rn(v0, bv.x); v0 = (v0 >= 0.f) ? v0 : __fmul_rn(0.01f, v0);
                v1 = __fadd_rn(v1, bv.y); v1 = (v1 >= 0.f) ? v1 : __fmul_rn(0.01f, v1);
                v2 = __fadd_rn(v2, bv.x); v2 = (v2 >= 0.f) ? v2 : __fmul_rn(0.01f, v2);
                v3 = __fadd_rn(v3, bv.y); v3 = (v3 >= 0.f) ? v3 : __fmul_rn(0.01f, v3);
            }
            if (rl < N) *(float2*)(Cout + (size_t)rl * LDC + col) = make_float2(v0, v1);
            if (rh < N) *(float2*)(Cout + (size_t)rh * LDC + col) = make_float2(v2, v3);
        }
    }
}

// conc = softplus(h2 @ W3 + b3) + 1e-20   (warp per row)
__global__ void k_conc(const float* __restrict__ W3, const float* __restrict__ b3, int N) {
    int row = blockIdx.x * 8 + (threadIdx.x >> 5);
    if (row >= N) return;
    int lane = threadIdx.x & 31;
    const float4* hr = (const float4*)(g_h2 + (size_t)row * 256);
    const float4* w4 = (const float4*)W3;
    float s = 0.f;
#pragma unroll
    for (int j = lane; j < 64; j += 32) {
        float4 a = hr[j], w = w4[j];
        s = fmaf(a.x, w.x, s); s = fmaf(a.y, w.y, s);
        s = fmaf(a.z, w.z, s); s = fmaf(a.w, w.w, s);
    }
#pragma unroll
    for (int o = 16; o; o >>= 1) s += __shfl_xor_sync(0xFFFFFFFFu, s, o);
    if (lane == 0) {
        float z = __fadd_rn(s, b3[0]);
        double sp = fmax((double)z, 0.0) + log1p(exp(-fabs((double)z)));
        g_conc[row] = __fadd_rn((float)sp, 1e-20f);
    }
}

// ------------------------- loggamma sampler (jax _gamma_one) -----------------
__global__ void k_sample(int N) {
    int i = blockIdx.x * blockDim.x + threadIdx.x;
    if (i >= N) return;
    float alpha = g_conc[i];
    K2 key = split_big(K2{0u, 42u}, (unsigned)i);

    bool boost = (alpha >= 1.0f);
    float alpha_b = boost ? alpha : __fadd_rn(alpha, 1.0f);
    const float third = 0.3333333433f;
    float d = __fsub_rn(alpha_b, third);
    float c = __fdiv_rn(third, __fsqrt_rn(d));

    K2 k0, sub;
    split2(key, k0, sub);
    key = k0;
    float u_boost = u01(sub);

    float V;
    for (;;) {
        K2 nk, xk, uk;
        split3(key, nk, xk, uk);
        key = nk;
        float x, v;
        K2 kk = xk;
        do {
            K2 a, b;
            split2(kk, a, b);
            kk = a;
            x = nrm(b);
            v = __fadd_rn(1.0f, __fmul_rn(c, x));
        } while (v <= 0.0f);
        float X = __fmul_rn(x, x);
        V = __fmul_rn(__fmul_rn(v, v), v);
        float U = u01(uk);
        float sq = __fsub_rn(1.0f, __fmul_rn(0.0331f, __fmul_rn(X, X)));
        if (U < sq) break;
        float logU = (float)log((double)U);
        float logV = (float)log((double)V);
        float rhs = __fadd_rn(__fmul_rn(X, 0.5f),
                              __fmul_rn(d, __fadd_rn(__fsub_rn(1.0f, V), logV)));
        if (logU < rhs) break;
    }
    float log_sample = __fadd_rn((float)log((double)d), (float)log((double)V));
    float lg;
    if (boost) lg = log_sample;
    else {
        float lb = __fmul_rn((float)log1p(-(double)u_boost), __fdiv_rn(1.0f, alpha));
        lg = __fadd_rn(log_sample, lb);
    }
    g_lg[i] = lg;
}

// ------------------------- per-row finish: softmax + log_prob ----------------
__global__ void k_row(float* __restrict__ out, int N, int writeLP) {
    int b = blockIdx.x;
    int t = threadIdx.x;
    __shared__ float  rf[256];
    __shared__ double rd[256];
    const float* lg = g_lg   + (size_t)b * ADIM;
    const float* cc = g_conc + (size_t)b * ADIM;

    float m = -1e30f;
    for (int j = t; j < ADIM; j += 256) m = fmaxf(m, lg[j]);
    rf[t] = m; __syncthreads();
    for (int s = 128; s; s >>= 1) { if (t < s) rf[t] = fmaxf(rf[t], rf[t + s]); __syncthreads(); }
    m = rf[0]; __syncthreads();

    float se = 0.f;
    for (int j = t; j < ADIM; j += 256)
        se = __fadd_rn(se, (float)exp((double)__fsub_rn(lg[j], m)));
    rf[t] = se; __syncthreads();
    for (int s = 128; s; s >>= 1) { if (t < s) rf[t] = __fadd_rn(rf[t], rf[t + s]); __syncthreads(); }
    float lse = __fadd_rn((float)log((double)rf[0]), m);
    __syncthreads();

    double t1 = 0.0, t3 = 0.0, sc = 0.0;
    for (int j = t; j < ADIM; j += 256) {
        float af = (float)exp((double)__fsub_rn(lg[j], lse));
        out[(size_t)b * ADIM + j] = af;
        float cj = cc[j];
        t1 += (double)__fsub_rn(cj, 1.0f) * log((double)af);
        t3 += (double)lgammaf(cj);
        sc += (double)cj;
    }
    rd[t] = t1; __syncthreads();
    for (int s = 128; s; s >>= 1) { if (t < s) rd[t] += rd[t + s]; __syncthreads(); }
    t1 = rd[0]; __syncthreads();
    rd[t] = t3; __syncthreads();
    for (int s = 128; s; s >>= 1) { if (t < s) rd[t] += rd[t + s]; __syncthreads(); }
    t3 = rd[0]; __syncthreads();
    rd[t] = sc; __syncthreads();
    for (int s = 128; s; s >>= 1) { if (t < s) rd[t] += rd[t + s]; __syncthreads(); }
    sc = rd[0];

    if (t == 0 && writeLP) {
        float scf = (float)sc;
        double lp = t1 + lgamma((double)scf) - t3;
        out[(size_t)N + b] = (float)lp;
    }
}

// ------------------------- launch -------------------------------------------
extern "C" void kernel_launch(void* const* d_in, const int* in_sizes, int n_in,
                              void* d_out, int out_size) {
    const float* x      = (const float*)d_in[0];
    const float* W_conv = (const float*)d_in[1];
    const float* b_conv = (const float*)d_in[2];
    const float* W1     = (const float*)d_in[3];
    const float* b1     = (const float*)d_in[4];
    const float* W2     = (const float*)d_in[5];
    const float* b2     = (const float*)d_in[6];
    const float* W3     = (const float*)d_in[7];
    const float* b3     = (const float*)d_in[8];
    const int*   ei     = (const int*)d_in[9];
    float* out = (float*)d_out;

    int N = in_sizes[0] / 128;
    int E = in_sizes[9] / 2;
    int B = N / ADIM;
    const int* src = ei;
    const int* dst = ei + E;

    k_deg_init<<<(N + 255) / 256, 256>>>(N);
    k_deg_count<<<(E + 255) / 256, 256>>>(dst, E);
    k_dinv<<<(N + 255) / 256, 256>>>(N);

    float* gh = nullptr; float* gh1 = nullptr; float* gh2 = nullptr;
    cudaGetSymbolAddress((void**)&gh,  g_h);
    cudaGetSymbolAddress((void**)&gh1, g_h1);
    cudaGetSymbolAddress((void**)&gh2, g_h2);

    int RB = (N + 127) / 128;
    dim3 g0(RB, 1), g1(RB, 2);

    // h = x @ Wc
    k_gemm<128,128,128,128,0><<<g0, 256>>>(x, W_conv, nullptr, gh, N);
    k_self<<<(N * 32 + 255) / 256, 256>>>(N * 32);
    k_scatter<<<(E + 7) / 8, 256>>>(src, dst, E);
    // g_h <- relu(agg + b_conv) + x
    k_prep<<<(N * 32 + 255) / 256, 256>>>(x, b_conv, N * 32);
    // h1 = leaky(g_h @ W1 + b1)
    k_gemm<128,256,128,256,1><<<g1, 256>>>(gh, W1, b1, gh1, N);
    // h2 = leaky(h1 @ W2 + b2)
    k_gemm<256,256,256,256,1><<<g1, 256>>>(gh1, W2, b2, gh2, N);
    k_conc<<<(N + 7) / 8, 256>>>(W3, b3, N);
    k_sample<<<(N + 127) / 128, 128>>>(N);
    int writeLP = (out_size >= N + B) ? 1 : 0;
    k_row<<<B, 256>>>(out, N, writeLP);
}

// round 17
// speedup vs baseline: 1.1670x; 1.1670x over previous
#include <cuda_runtime.h>
#include <math.h>
#include <stdint.h>

#define NN_MAX 100000
#define ADIM   1000

// ------------------------- scratch (no runtime alloc) -----------------------
__device__ float g_h   [(size_t)NN_MAX*128];
__device__ float g_agg [(size_t)NN_MAX*128];
__device__ float g_h1  [(size_t)NN_MAX*256];
__device__ float g_h2  [(size_t)NN_MAX*256];
__device__ float g_deg [NN_MAX];
__device__ float g_dinv[NN_MAX];
__device__ float g_conc[NN_MAX];
__device__ float g_lg  [NN_MAX];

// ------------------------- threefry2x32 (JAX-exact) -------------------------
struct K2 { unsigned a, b; };

__device__ __forceinline__ void tf_round(unsigned &x0, unsigned &x1, int r) {
    x0 += x1;
    x1 = (x1 << r) | (x1 >> (32 - r));
    x1 ^= x0;
}
__device__ __forceinline__ K2 tf_block(unsigned k0, unsigned k1, unsigned x0, unsigned x1) {
    unsigned k2 = k0 ^ k1 ^ 0x1BD11BDAu;
    x0 += k0; x1 += k1;
    tf_round(x0,x1,13); tf_round(x0,x1,15); tf_round(x0,x1,26); tf_round(x0,x1,6);
    x0 += k1; x1 += k2 + 1u;
    tf_round(x0,x1,17); tf_round(x0,x1,29); tf_round(x0,x1,16); tf_round(x0,x1,24);
    x0 += k2; x1 += k0 + 2u;
    tf_round(x0,x1,13); tf_round(x0,x1,15); tf_round(x0,x1,26); tf_round(x0,x1,6);
    x0 += k0; x1 += k1 + 3u;
    tf_round(x0,x1,17); tf_round(x0,x1,29); tf_round(x0,x1,16); tf_round(x0,x1,24);
    x0 += k1; x1 += k2 + 4u;
    tf_round(x0,x1,13); tf_round(x0,x1,15); tf_round(x0,x1,26); tf_round(x0,x1,6);
    x0 += k2; x1 += k0 + 5u;
    K2 r; r.a = x0; r.b = x1; return r;
}
__device__ __forceinline__ unsigned rbits(K2 k) {
    K2 r = tf_block(k.a, k.b, 0u, 0u);
    return r.a ^ r.b;
}
__device__ __forceinline__ void split2(K2 k, K2 &o0, K2 &o1) {
    o0 = tf_block(k.a, k.b, 0u, 0u);
    o1 = tf_block(k.a, k.b, 0u, 1u);
}
__device__ __forceinline__ void split3(K2 k, K2 &o0, K2 &o1, K2 &o2) {
    o0 = tf_block(k.a, k.b, 0u, 0u);
    o1 = tf_block(k.a, k.b, 0u, 1u);
    o2 = tf_block(k.a, k.b, 0u, 2u);
}
__device__ __forceinline__ K2 split_big(K2 k, unsigned i) {
    return tf_block(k.a, k.b, 0u, i);
}
__device__ __forceinline__ float u01(K2 k) {
    unsigned bits = rbits(k);
    return __uint_as_float((bits >> 9) | 0x3f800000u) - 1.0f;
}
__device__ __forceinline__ float erfinv_xla(float x) {
    float xx = __fmul_rn(x, x);
    float w = (float)(-log1p(-(double)xx));
    float p;
    if (w < 5.0f) {
        w = __fsub_rn(w, 2.5f);
        p = 2.81022636e-08f;
        p = fmaf(p, w, 3.43273939e-07f);
        p = fmaf(p, w, -3.5233877e-06f);
        p = fmaf(p, w, -4.39150654e-06f);
        p = fmaf(p, w, 0.00021858087f);
        p = fmaf(p, w, -0.00125372503f);
        p = fmaf(p, w, -0.00417768164f);
        p = fmaf(p, w, 0.246640727f);
        p = fmaf(p, w, 1.50140941f);
    } else {
        w = __fsub_rn(__fsqrt_rn(w), 3.0f);
        p = -0.000200214257f;
        p = fmaf(p, w, 0.000100950558f);
        p = fmaf(p, w, 0.00134934322f);
        p = fmaf(p, w, -0.00367342844f);
        p = fmaf(p, w, 0.00573950773f);
        p = fmaf(p, w, -0.0076224613f);
        p = fmaf(p, w, 0.00943887047f);
        p = fmaf(p, w, 1.00167406f);
        p = fmaf(p, w, 2.83297682f);
    }
    return __fmul_rn(p, x);
}
__device__ __forceinline__ float nrm(K2 k) {
    float f = u01(k);
    const float lo = __uint_as_float(0xBF7FFFFFu);
    float v = __fadd_rn(__fmul_rn(f, 2.0f), lo);
    v = fmaxf(lo, v);
    return __fmul_rn(__uint_as_float(0x3FB504F3u), erfinv_xla(v));
}

// ------------------------- degree / norm ------------------------------------
__global__ void k_deg_init(int n) {
    int i = blockIdx.x * blockDim.x + threadIdx.x;
    if (i < n) g_deg[i] = 1.0f;
}
__global__ void k_deg_count(const int* __restrict__ dst, int E) {
    int e = blockIdx.x * blockDim.x + threadIdx.x;
    if (e < E) atomicAdd(&g_deg[dst[e]], 1.0f);
}
__global__ void k_dinv(int n) {
    int i = blockIdx.x * blockDim.x + threadIdx.x;
    if (i < n) g_dinv[i] = (float)(1.0 / sqrt((double)g_deg[i]));
}
__global__ void k_self(int n4) {
    int idx = blockIdx.x * blockDim.x + threadIdx.x;
    if (idx >= n4) return;
    int node = idx >> 5;
    float di = g_dinv[node];
    float n2 = __fmul_rn(di, di);
    float4 v = ((const float4*)g_h)[idx];
    float4 o;
    o.x = __fmul_rn(v.x, n2); o.y = __fmul_rn(v.y, n2);
    o.z = __fmul_rn(v.z, n2); o.w = __fmul_rn(v.w, n2);
    ((float4*)g_agg)[idx] = o;
}
__global__ void k_scatter(const int* __restrict__ src, const int* __restrict__ dst, int E) {
    int e = blockIdx.x * 8 + (threadIdx.x >> 5);
    if (e >= E) return;
    int lane = threadIdx.x & 31;
    int s = __ldg(&src[e]);
    int d = __ldg(&dst[e]);
    float norm = __fmul_rn(g_dinv[s], g_dinv[d]);
    float4 v = *(const float4*)(g_h + (size_t)s * 128 + lane * 4);
    float* out = g_agg + (size_t)d * 128 + lane * 4;
    float m0 = __fmul_rn(v.x, norm);
    float m1 = __fmul_rn(v.y, norm);
    float m2 = __fmul_rn(v.z, norm);
    float m3 = __fmul_rn(v.w, norm);
    asm volatile("red.global.add.v4.f32 [%0], {%1,%2,%3,%4};"
                 :: "l"(out), "f"(m0), "f"(m1), "f"(m2), "f"(m3) : "memory");
}
__global__ void k_prep(const float* __restrict__ x, const float* __restrict__ bc, int n4) {
    int idx = blockIdx.x * blockDim.x + threadIdx.x;
    if (idx >= n4) return;
    int c4 = (idx & 31);
    float4 g = ((const float4*)g_agg)[idx];
    float4 xv = ((const float4*)x)[idx];
    float4 b = ((const float4*)bc)[c4];
    float4 o;
    o.x = __fadd_rn(fmaxf(__fadd_rn(g.x, b.x), 0.f), xv.x);
    o.y = __fadd_rn(fmaxf(__fadd_rn(g.y, b.y), 0.f), xv.y);
    o.z = __fadd_rn(fmaxf(__fadd_rn(g.z, b.z), 0.f), xv.z);
    o.w = __fadd_rn(fmaxf(__fadd_rn(g.w, b.w), 0.f), xv.w);
    ((float4*)g_h)[idx] = o;
}

// ------------------------- 3xTF32 mma.sync GEMM -----------------------------
// R14 core (best: 747.6us) + W-fragment double-buffering across the n loop
// (prefetch n+1's W fragments while n's MMAs execute; R8-validated pattern).
// CTA 128x128, warp 32x64, 2 CTA/SM, K-slice 8, 2-buf smem.
// A hi/lo row-major pitch 12; W hi/lo k-major pitch 136 (both conflict-free).
// EPI=0: C = A@W.  EPI=1: C = leaky(A@W + bout).
#define PSW 136
#define PSA 12

__device__ __forceinline__ uint32_t f2tf(float x) {
    uint32_t r;
    asm("cvt.rna.tf32.f32 %0, %1;" : "=r"(r) : "f"(x));
    return r;
}

#define MMA_TF32(c, a, b0, b1) \
    asm volatile("mma.sync.aligned.m16n8k8.row.col.f32.tf32.tf32.f32 " \
                 "{%0,%1,%2,%3}, {%4,%5,%6,%7}, {%8,%9}, {%0,%1,%2,%3};" \
                 : "+f"((c)[0]), "+f"((c)[1]), "+f"((c)[2]), "+f"((c)[3]) \
                 : "r"((a)[0]), "r"((a)[1]), "r"((a)[2]), "r"((a)[3]), \
                   "r"(b0), "r"(b1))

template<int K, int LDW, int LDA, int LDC, int EPI>
__global__ void __launch_bounds__(256, 2) k_gemm(const float* __restrict__ A,
                                                 const float* __restrict__ W,
                                                 const float* __restrict__ bout,
                                                 float* __restrict__ Cout, int N) {
    __shared__ uint32_t sAh[2][128 * PSA];
    __shared__ uint32_t sAl[2][128 * PSA];
    __shared__ uint32_t sWh[2][8 * PSW];
    __shared__ uint32_t sWl[2][8 * PSW];

    const int t    = threadIdx.x;
    const int row0 = blockIdx.x * 128;
    const int c0   = blockIdx.y * 128;
    const int S    = K / 8;

    // loader indices
    const int lr   = t >> 1;               // A row 0..127
    const int lk4  = (t & 1) * 4;          // A k-offset 0/4
    const int wk   = t >> 5;               // W k-row 0..7
    const int wc4  = (t & 31) * 4;         // W col
    const bool aok = (row0 + lr) < N;
    const float* Ap = A + (size_t)(row0 + lr) * LDA + lk4;
    const float* Wp = W + (size_t)wk * LDW + c0 + wc4;

    // compute indices
    const int lane = t & 31;
    const int g    = lane >> 2;
    const int tig  = lane & 3;
    const int wid  = t >> 5;
    const int wm   = wid & 3;              // 4 warps along M
    const int wn   = wid >> 2;             // 2 warps along N
    const int rowb = wm * 32;
    const int colb = wn * 64;

    float acc[2][8][4];
#pragma unroll
    for (int m = 0; m < 2; m++)
#pragma unroll
        for (int n = 0; n < 8; n++)
#pragma unroll
            for (int q = 0; q < 4; q++) acc[m][n][q] = 0.f;

    float4 va = make_float4(0.f, 0.f, 0.f, 0.f), vw;
    if (aok) va = *(const float4*)(Ap);
    vw = *(const float4*)(Wp);

    // split+store registers -> smem buffer b (vectorized STS.128)
    auto sstore = [&](int b) {
        const float* vaf = (const float*)&va;
        const float* vwf = (const float*)&vw;
        uint4 ha, la, hw, lw;
        uint32_t* pha = (uint32_t*)&ha; uint32_t* pla = (uint32_t*)&la;
        uint32_t* phw = (uint32_t*)&hw; uint32_t* plw = (uint32_t*)&lw;
#pragma unroll
        for (int j = 0; j < 4; j++) {
            float x = vaf[j];
            uint32_t hi = f2tf(x);
            pha[j] = hi;
            pla[j] = f2tf(__fsub_rn(x, __uint_as_float(hi)));
            float y = vwf[j];
            uint32_t hy = f2tf(y);
            phw[j] = hy;
            plw[j] = f2tf(__fsub_rn(y, __uint_as_float(hy)));
        }
        *(uint4*)&sAh[b][lr * PSA + lk4] = ha;
        *(uint4*)&sAl[b][lr * PSA + lk4] = la;
        *(uint4*)&sWh[b][wk * PSW + wc4] = hw;
        *(uint4*)&sWl[b][wk * PSW + wc4] = lw;
    };

    sstore(0);
    __syncthreads();

    for (int s = 0; s < S; s++) {
        const int buf = s & 1;
        if (s + 1 < S) {
            int kc = (s + 1) * 8;
            va = make_float4(0.f, 0.f, 0.f, 0.f);
            if (aok) va = *(const float4*)(Ap + kc);
            vw = *(const float4*)(Wp + (size_t)kc * LDW);
        }

        // A fragments (hi+lo): banks 12g+tig form a complete residue system
        uint32_t ah[2][4], al[2][4];
#pragma unroll
        for (int m = 0; m < 2; m++) {
            int rb = rowb + m * 16 + g;
            int b0 = rb * PSA;
            int b1 = (rb + 8) * PSA;
            ah[m][0] = sAh[buf][b0 + tig];
            ah[m][1] = sAh[buf][b1 + tig];
            ah[m][2] = sAh[buf][b0 + tig + 4];
            ah[m][3] = sAh[buf][b1 + tig + 4];
            al[m][0] = sAl[buf][b0 + tig];
            al[m][1] = sAl[buf][b1 + tig];
            al[m][2] = sAl[buf][b0 + tig + 4];
            al[m][3] = sAl[buf][b1 + tig + 4];
        }

        // W fragments: double-buffered across the n loop (prefetch n+1)
        uint32_t bh0[2], bh1[2], bl0[2], bl1[2];
        {
            int col = colb + g;
            bh0[0] = sWh[buf][tig * PSW + col];
            bh1[0] = sWh[buf][(tig + 4) * PSW + col];
            bl0[0] = sWl[buf][tig * PSW + col];
            bl1[0] = sWl[buf][(tig + 4) * PSW + col];
        }
#pragma unroll
        for (int n = 0; n < 8; n++) {
            const int cur = n & 1, nxt = cur ^ 1;
            if (n + 1 < 8) {
                int col = colb + (n + 1) * 8 + g;
                bh0[nxt] = sWh[buf][tig * PSW + col];
                bh1[nxt] = sWh[buf][(tig + 4) * PSW + col];
                bl0[nxt] = sWl[buf][tig * PSW + col];
                bl1[nxt] = sWl[buf][(tig + 4) * PSW + col];
            }
#pragma unroll
            for (int m = 0; m < 2; m++) {
                MMA_TF32(acc[m][n], ah[m], bh0[cur], bh1[cur]);
                MMA_TF32(acc[m][n], ah[m], bl0[cur], bl1[cur]);
                MMA_TF32(acc[m][n], al[m], bh0[cur], bh1[cur]);
            }
        }

        if (s + 1 < S) sstore(buf ^ 1);
        __syncthreads();
    }

    // epilogue
#pragma unroll
    for (int m = 0; m < 2; m++) {
#pragma unroll
        for (int n = 0; n < 8; n++) {
            int rl  = row0 + rowb + m * 16 + g;
            int rh  = rl + 8;
            int col = c0 + colb + n * 8 + 2 * tig;
            float2 bv = make_float2(0.f, 0.f);
            if (EPI) bv = *(const float2*)(bout + col);
            float v0 = acc[m][n][0], v1 = acc[m][n][1];
            float v2 = acc[m][n][2], v3 = acc[m][n][3];
            if (EPI) {
                v0 = __fadd_rn(v0, bv.x); v0 = (v0 >= 0.f) ? v0 : __fmul_rn(0.01f, v0);
                v1 = __fadd_rn(v1, bv.y); v1 = (v1 >= 0.f) ? v1 : __fmul_rn(0.01f, v1);
                v2 = __fadd_rn(v2, bv.x); v2 = (v2 >= 0.f) ? v2 : __fmul_rn(0.01f, v2);
                v3 = __fadd_rn(v3, bv.y); v3 = (v3 >= 0.f) ? v3 : __fmul_rn(0.01f, v3);
            }
            if (rl < N) *(float2*)(Cout + (size_t)rl * LDC + col) = make_float2(v0, v1);
            if (rh < N) *(float2*)(Cout + (size_t)rh * LDC + col) = make_float2(v2, v3);
        }
    }
}

// conc = softplus(h2 @ W3 + b3) + 1e-20   (warp per row)
__global__ void k_conc(const float* __restrict__ W3, const float* __restrict__ b3, int N) {
    int row = blockIdx.x * 8 + (threadIdx.x >> 5);
    if (row >= N) return;
    int lane = threadIdx.x & 31;
    const float4* hr = (const float4*)(g_h2 + (size_t)row * 256);
    const float4* w4 = (const float4*)W3;
    float s = 0.f;
#pragma unroll
    for (int j = lane; j < 64; j += 32) {
        float4 a = hr[j], w = w4[j];
        s = fmaf(a.x, w.x, s); s = fmaf(a.y, w.y, s);
        s = fmaf(a.z, w.z, s); s = fmaf(a.w, w.w, s);
    }
#pragma unroll
    for (int o = 16; o; o >>= 1) s += __shfl_xor_sync(0xFFFFFFFFu, s, o);
    if (lane == 0) {
        float z = __fadd_rn(s, b3[0]);
        double sp = fmax((double)z, 0.0) + log1p(exp(-fabs((double)z)));
        g_conc[row] = __fadd_rn((float)sp, 1e-20f);
    }
}

// ------------------------- loggamma sampler (jax _gamma_one) -----------------
__global__ void k_sample(int N) {
    int i = blockIdx.x * blockDim.x + threadIdx.x;
    if (i >= N) return;
    float alpha = g_conc[i];
    K2 key = split_big(K2{0u, 42u}, (unsigned)i);

    bool boost = (alpha >= 1.0f);
    float alpha_b = boost ? alpha : __fadd_rn(alpha, 1.0f);
    const float third = 0.3333333433f;
    float d = __fsub_rn(alpha_b, third);
    float c = __fdiv_rn(third, __fsqrt_rn(d));

    K2 k0, sub;
    split2(key, k0, sub);
    key = k0;
    float u_boost = u01(sub);

    float V;
    for (;;) {
        K2 nk, xk, uk;
        split3(key, nk, xk, uk);
        key = nk;
        float x, v;
        K2 kk = xk;
        do {
            K2 a, b;
            split2(kk, a, b);
            kk = a;
            x = nrm(b);
            v = __fadd_rn(1.0f, __fmul_rn(c, x));
        } while (v <= 0.0f);
        float X = __fmul_rn(x, x);
        V = __fmul_rn(__fmul_rn(v, v), v);
        float U = u01(uk);
        float sq = __fsub_rn(1.0f, __fmul_rn(0.0331f, __fmul_rn(X, X)));
        if (U < sq) break;
        float logU = (float)log((double)U);
        float logV = (float)log((double)V);
        float rhs = __fadd_rn(__fmul_rn(X, 0.5f),
                              __fmul_rn(d, __fadd_rn(__fsub_rn(1.0f, V), logV)));
        if (logU < rhs) break;
    }
    float log_sample = __fadd_rn((float)log((double)d), (float)log((double)V));
    float lg;
    if (boost) lg = log_sample;
    else {
        float lb = __fmul_rn((float)log1p(-(double)u_boost), __fdiv_rn(1.0f, alpha));
        lg = __fadd_rn(log_sample, lb);
    }
    g_lg[i] = lg;
}

// ------------------------- per-row finish: softmax + log_prob ----------------
__global__ void k_row(float* __restrict__ out, int N, int writeLP) {
    int b = blockIdx.x;
    int t = threadIdx.x;
    __shared__ float  rf[256];
    __shared__ double rd[256];
    const float* lg = g_lg   + (size_t)b * ADIM;
    const float* cc = g_conc + (size_t)b * ADIM;

    float m = -1e30f;
    for (int j = t; j < ADIM; j += 256) m = fmaxf(m, lg[j]);
    rf[t] = m; __syncthreads();
    for (int s = 128; s; s >>= 1) { if (t < s) rf[t] = fmaxf(rf[t], rf[t + s]); __syncthreads(); }
    m = rf[0]; __syncthreads();

    float se = 0.f;
    for (int j = t; j < ADIM; j += 256)
        se = __fadd_rn(se, (float)exp((double)__fsub_rn(lg[j], m)));
    rf[t] = se; __syncthreads();
    for (int s = 128; s; s >>= 1) { if (t < s) rf[t] = __fadd_rn(rf[t], rf[t + s]); __syncthreads(); }
    float lse = __fadd_rn((float)log((double)rf[0]), m);
    __syncthreads();

    double t1 = 0.0, t3 = 0.0, sc = 0.0;
    for (int j = t; j < ADIM; j += 256) {
        float af = (float)exp((double)__fsub_rn(lg[j], lse));
        out[(size_t)b * ADIM + j] = af;
        float cj = cc[j];
        t1 += (double)__fsub_rn(cj, 1.0f) * log((double)af);
        t3 += (double)lgammaf(cj);
        sc += (double)cj;
    }
    rd[t] = t1; __syncthreads();
    for (int s = 128; s; s >>= 1) { if (t < s) rd[t] += rd[t + s]; __syncthreads(); }
    t1 = rd[0]; __syncthreads();
    rd[t] = t3; __syncthreads();
    for (int s = 128; s; s >>= 1) { if (t < s) rd[t] += rd[t + s]; __syncthreads(); }
    t3 = rd[0]; __syncthreads();
    rd[t] = sc; __syncthreads();
    for (int s = 128; s; s >>= 1) { if (t < s) rd[t] += rd[t + s]; __syncthreads(); }
    sc = rd[0];

    if (t == 0 && writeLP) {
        float scf = (float)sc;
        double lp = t1 + lgamma((double)scf) - t3;
        out[(size_t)N + b] = (float)lp;
    }
}

// ------------------------- launch -------------------------------------------
extern "C" void kernel_launch(void* const* d_in, const int* in_sizes, int n_in,
                              void* d_out, int out_size) {
    const float* x      = (const float*)d_in[0];
    const float* W_conv = (const float*)d_in[1];
    const float* b_conv = (const float*)d_in[2];
    const float* W1     = (const float*)d_in[3];
    const float* b1     = (const float*)d_in[4];
    const float* W2     = (const float*)d_in[5];
    const float* b2     = (const float*)d_in[6];
    const float* W3     = (const float*)d_in[7];
    const float* b3     = (const float*)d_in[8];
    const int*   ei     = (const int*)d_in[9];
    float* out = (float*)d_out;

    int N = in_sizes[0] / 128;
    int E = in_sizes[9] / 2;
    int B = N / ADIM;
    const int* src = ei;
    const int* dst = ei + E;

    k_deg_init<<<(N + 255) / 256, 256>>>(N);
    k_deg_count<<<(E + 255) / 256, 256>>>(dst, E);
    k_dinv<<<(N + 255) / 256, 256>>>(N);

    float* gh = nullptr; float* gh1 = nullptr; float* gh2 = nullptr;
    cudaGetSymbolAddress((void**)&gh,  g_h);
    cudaGetSymbolAddress((void**)&gh1, g_h1);
    cudaGetSymbolAddress((void**)&gh2, g_h2);

    int RB = (N + 127) / 128;
    dim3 g0(RB, 1), g1(RB, 2);

    // h = x @ Wc
    k_gemm<128,128,128,128,0><<<g0, 256>>>(x, W_conv, nullptr, gh, N);
    k_self<<<(N * 32 + 255) / 256, 256>>>(N * 32);
    k_scatter<<<(E + 7) / 8, 256>>>(src, dst, E);
    // g_h <- relu(agg + b_conv) + x
    k_prep<<<(N * 32 + 255) / 256, 256>>>(x, b_conv, N * 32);
    // h1 = leaky(g_h @ W1 + b1)
    k_gemm<128,256,128,256,1><<<g1, 256>>>(gh, W1, b1, gh1, N);
    // h2 = leaky(h1 @ W2 + b2)
    k_gemm<256,256,256,256,1><<<g1, 256>>>(gh1, W2, b2, gh2, N);
    k_conc<<<(N + 7) / 8, 256>>>(W3, b3, N);
    k_sample<<<(N + 127) / 128, 128>>>(N);
    int writeLP = (out_size >= N + B) ? 1 : 0;
    k_row<<<B, 256>>>(out, N, writeLP);
}